// round 2
// baseline (speedup 1.0000x reference)
#include <cuda_runtime.h>
#include <math.h>

#define B 512
#define MBD_B 64
#define MBD_C 16
#define FEAT 640

// ---------------- scratch (device globals; no allocation) ----------------
__device__ float g_h1[B * 20 * 12 * 12];     // conv1+pool output
__device__ float g_feats[B * FEAT];          // conv2+pool output, [b][oc*16+y*4+x]
__device__ float g_M[B * MBD_B * MBD_C];     // feats @ T^T, [b][1024]
__device__ float g_close[B * MBD_B];         // closeness [b][64]

// ---------------- K1: conv1 (1->20, 5x5) + relu + maxpool2 ----------------
// one block per image, 240 active threads = 20 oc x 12 pooled-rows
__global__ __launch_bounds__(256) void k_conv1(const float* __restrict__ x,
                                               const float* __restrict__ w,
                                               const float* __restrict__ bias) {
    __shared__ float img[784];
    __shared__ float ws[500];
    __shared__ float bs[20];
    int b = blockIdx.x, tid = threadIdx.x;
    const float* xb = x + b * 784;
    for (int i = tid; i < 784; i += 256) img[i] = xb[i];
    for (int i = tid; i < 500; i += 256) ws[i] = w[i];
    if (tid < 20) bs[tid] = bias[tid];
    __syncthreads();
    if (tid >= 240) return;
    int oc = tid / 12, py = tid % 12;
    float acc[2][24];
    float bv = bs[oc];
    #pragma unroll
    for (int cy = 0; cy < 2; cy++)
        #pragma unroll
        for (int ox = 0; ox < 24; ox++) acc[cy][ox] = bv;
    #pragma unroll 1
    for (int ky = 0; ky < 5; ky++) {
        float wk[5];
        #pragma unroll
        for (int kx = 0; kx < 5; kx++) wk[kx] = ws[(oc * 5 + ky) * 5 + kx];
        #pragma unroll
        for (int cy = 0; cy < 2; cy++) {
            const float* r = img + (2 * py + cy + ky) * 28;
            float rr[28];
            #pragma unroll
            for (int i = 0; i < 28; i++) rr[i] = r[i];
            #pragma unroll
            for (int kx = 0; kx < 5; kx++)
                #pragma unroll
                for (int ox = 0; ox < 24; ox++)
                    acc[cy][ox] += rr[ox + kx] * wk[kx];
        }
    }
    float* out = g_h1 + (b * 20 + oc) * 144 + py * 12;
    #pragma unroll
    for (int px = 0; px < 12; px++) {
        float v = fmaxf(fmaxf(acc[0][2 * px], acc[0][2 * px + 1]),
                        fmaxf(acc[1][2 * px], acc[1][2 * px + 1]));
        out[px] = fmaxf(v, 0.f);
    }
}

// ---------------- K2: conv2 (20->40, 5x5) + relu + maxpool2 ----------------
// one block per image, 160 threads = 40 oc x 4 pooled-rows
// dynamic smem: input 2880 floats + weights 20000 floats = 91520 B
__global__ __launch_bounds__(160) void k_conv2(const float* __restrict__ w,
                                               const float* __restrict__ bias) {
    extern __shared__ float sm[];
    float* in2 = sm;          // 2880
    float* ws = sm + 2880;    // 20000
    int b = blockIdx.x, tid = threadIdx.x;
    const float* src = g_h1 + b * 2880;
    for (int i = tid; i < 2880; i += 160) in2[i] = src[i];
    const float4* w4 = (const float4*)w;
    float4* ws4 = (float4*)ws;
    for (int i = tid; i < 5000; i += 160) ws4[i] = w4[i];
    __syncthreads();

    int oc = tid / 4, py = tid % 4;
    float acc[2][8];
    float bv = bias[oc];
    #pragma unroll
    for (int cy = 0; cy < 2; cy++)
        #pragma unroll
        for (int ox = 0; ox < 8; ox++) acc[cy][ox] = bv;

    #pragma unroll 1
    for (int ic = 0; ic < 20; ic++) {
        #pragma unroll 1
        for (int ky = 0; ky < 5; ky++) {
            const float* wr = ws + ((oc * 20 + ic) * 5 + ky) * 5;
            float wk[5];
            #pragma unroll
            for (int kx = 0; kx < 5; kx++) wk[kx] = wr[kx];
            #pragma unroll
            for (int cy = 0; cy < 2; cy++) {
                const float* r = in2 + ic * 144 + (2 * py + cy + ky) * 12;
                float rr[12];
                #pragma unroll
                for (int i = 0; i < 12; i++) rr[i] = r[i];
                #pragma unroll
                for (int kx = 0; kx < 5; kx++)
                    #pragma unroll
                    for (int ox = 0; ox < 8; ox++)
                        acc[cy][ox] += rr[ox + kx] * wk[kx];
            }
        }
    }
    float* fo = g_feats + b * 640 + oc * 16 + py * 4;
    #pragma unroll
    for (int px = 0; px < 4; px++) {
        float v = fmaxf(fmaxf(acc[0][2 * px], acc[0][2 * px + 1]),
                        fmaxf(acc[1][2 * px], acc[1][2 * px + 1]));
        fo[px] = fmaxf(v, 0.f);
    }
}

// ---------------- K3: M = feats @ T^T  [512,640]x[1024,640]^T -> [512,1024] -------
#define BM 64
#define BN 64
#define BKK 32
__global__ __launch_bounds__(256) void k_gemm(const float* __restrict__ Tm) {
    __shared__ float As[BKK][BM];
    __shared__ float Bs[BKK][BN];
    int bn = blockIdx.x, bm = blockIdx.y;
    int tid = threadIdx.x;
    int tx = tid % 16, ty = tid / 16;
    float acc[4][4] = {};
    const float* A = g_feats + (bm * BM) * FEAT;
    const float* Bmat = Tm + (bn * BN) * FEAT;
    for (int k0 = 0; k0 < FEAT; k0 += BKK) {
        #pragma unroll
        for (int i = 0; i < 2; i++) {
            int t = tid + i * 256;
            int m = t / 8, kq = t % 8;
            float4 v = *(const float4*)(A + m * FEAT + k0 + kq * 4);
            As[kq * 4 + 0][m] = v.x; As[kq * 4 + 1][m] = v.y;
            As[kq * 4 + 2][m] = v.z; As[kq * 4 + 3][m] = v.w;
            float4 u = *(const float4*)(Bmat + m * FEAT + k0 + kq * 4);
            Bs[kq * 4 + 0][m] = u.x; Bs[kq * 4 + 1][m] = u.y;
            Bs[kq * 4 + 2][m] = u.z; Bs[kq * 4 + 3][m] = u.w;
        }
        __syncthreads();
        #pragma unroll
        for (int kk = 0; kk < BKK; kk++) {
            float a[4], bb[4];
            #pragma unroll
            for (int i = 0; i < 4; i++) a[i] = As[kk][ty * 4 + i];
            #pragma unroll
            for (int j = 0; j < 4; j++) bb[j] = Bs[kk][tx * 4 + j];
            #pragma unroll
            for (int i = 0; i < 4; i++)
                #pragma unroll
                for (int j = 0; j < 4; j++) acc[i][j] += a[i] * bb[j];
        }
        __syncthreads();
    }
    #pragma unroll
    for (int i = 0; i < 4; i++)
        #pragma unroll
        for (int j = 0; j < 4; j++)
            g_M[(bm * BM + ty * 4 + i) * 1024 + bn * BN + tx * 4 + j] = acc[i][j];
}

// ---------------- K4: minibatch discrimination closeness ----------------
// grid (64 b-cols, 4 i-tiles), 128 threads; stage M[:, b, :] (32KB) once
__global__ __launch_bounds__(128) void k_mbd() {
    __shared__ float s[512 * 16];
    int bcol = blockIdx.x;
    int itile = blockIdx.y;
    int tid = threadIdx.x;
    const float4* Ms = (const float4*)g_M;
    float4* s4 = (float4*)s;
    for (int t = tid; t < 512 * 4; t += 128) {
        int j = t >> 2, q = t & 3;
        s4[t] = Ms[(j * 1024 + bcol * 16) / 4 + q];
    }
    __syncthreads();
    int i = itile * 128 + tid;
    float m[16];
    #pragma unroll
    for (int c = 0; c < 16; c++) m[c] = s[i * 16 + c];
    float acc = 0.f;
    #pragma unroll 4
    for (int j = 0; j < 512; j++) {
        float d = 0.f;
        const float* sj = s + j * 16;
        #pragma unroll
        for (int c = 0; c < 16; c++) d += fabsf(m[c] - sj[c]);
        acc += __expf(-d);
    }
    g_close[i * 64 + bcol] = acc;
}

// ---------------- K5: concat + fc1 + relu + fc2 + sigmoid ----------------
// grid 64 blocks x 8 batch rows, 256 threads
__global__ __launch_bounds__(256) void k_fc(const float* __restrict__ w1,
                                            const float* __restrict__ b1,
                                            const float* __restrict__ w2,
                                            const float* __restrict__ b2,
                                            float* __restrict__ out) {
    __shared__ float sin_[8][704];
    __shared__ float h[8][100];
    int row0 = blockIdx.x * 8;
    int tid = threadIdx.x;
    for (int t = tid; t < 8 * 704; t += 256) {
        int r = t / 704, c = t % 704;
        sin_[r][c] = (c < 640) ? g_feats[(row0 + r) * 640 + c]
                               : g_close[(row0 + r) * 64 + (c - 640)];
    }
    __syncthreads();
    for (int o = tid; o < 800; o += 256) {
        int r = o / 100, c = o % 100;
        const float4* wrow = (const float4*)(w1 + c * 704);
        const float4* xin = (const float4*)(&sin_[r][0]);
        float acc = 0.f;
        #pragma unroll 4
        for (int k = 0; k < 176; k++) {
            float4 wv = wrow[k], xv = xin[k];
            acc += wv.x * xv.x + wv.y * xv.y + wv.z * xv.z + wv.w * xv.w;
        }
        h[r][c] = fmaxf(acc + b1[c], 0.f);
    }
    __syncthreads();
    int w = tid / 32, lane = tid % 32;
    if (w < 8) {
        float a = 0.f;
        for (int c = lane; c < 100; c += 32) a += h[w][c] * w2[c];
        #pragma unroll
        for (int off = 16; off; off >>= 1) a += __shfl_down_sync(0xffffffffu, a, off);
        if (lane == 0) {
            float z = a + b2[0];
            out[row0 + w] = 1.f / (1.f + __expf(-z));
        }
    }
}

// ---------------- launch ----------------
extern "C" void kernel_launch(void* const* d_in, const int* in_sizes, int n_in,
                              void* d_out, int out_size) {
    const float* x       = (const float*)d_in[0];
    const float* conv1_w = (const float*)d_in[1];
    const float* conv1_b = (const float*)d_in[2];
    const float* conv2_w = (const float*)d_in[3];
    const float* conv2_b = (const float*)d_in[4];
    const float* Tm      = (const float*)d_in[5];
    const float* fc1_w   = (const float*)d_in[6];
    const float* fc1_b   = (const float*)d_in[7];
    const float* fc2_w   = (const float*)d_in[8];
    const float* fc2_b   = (const float*)d_in[9];
    float* out = (float*)d_out;

    static int smem_set = 0;
    cudaFuncSetAttribute(k_conv2, cudaFuncAttributeMaxDynamicSharedMemorySize, 91520);
    (void)smem_set;

    k_conv1<<<B, 256>>>(x, conv1_w, conv1_b);
    k_conv2<<<B, 160, 91520>>>(conv2_w, conv2_b);
    dim3 g3(1024 / BN, B / BM);
    k_gemm<<<g3, 256>>>(Tm);
    dim3 g4(64, 4);
    k_mbd<<<g4, 128>>>();
    k_fc<<<64, 256>>>(fc1_w, fc1_b, fc2_w, fc2_b, out);
}

// round 3
// speedup vs baseline: 1.3027x; 1.3027x over previous
#include <cuda_runtime.h>
#include <math.h>

#define B 512
#define MBD_B 64
#define MBD_C 16
#define FEAT 640

// ---------------- scratch (device globals; no allocation) ----------------
__device__ float g_h1[B * 20 * 12 * 12];      // conv1+pool output [img][ic20][12][12]
__device__ float g_w2[20 * 40 * 5 * 8];       // repacked conv2 weights [ic][oc][ky][kx pad8]
__device__ float g_p2[2 * B * 40 * 64];       // conv2 pre-pool partials [ihalf][img][oc][y*8+x]
__device__ float g_feats[B * FEAT];           // conv2+pool output, [img][oc*16+y*4+x]
__device__ float g_M[B * MBD_B * MBD_C];      // feats @ T^T, [i][1024]
__device__ float g_closep[4 * B * MBD_B];     // closeness partials [jc][i][64]

// ---------------- K0: repack conv2 weights: w[oc][ic][ky][kx5] -> g_w2[ic][oc][ky][kx8]
__global__ __launch_bounds__(256) void k_repack(const float* __restrict__ w) {
    int g = blockIdx.x * 256 + threadIdx.x;          // (ic,oc,ky) group
    if (g >= 20 * 40 * 5) return;
    int ic = g / 200, oc = (g / 5) % 40, ky = g % 5;
    const float* src = w + ((oc * 20 + ic) * 5 + ky) * 5;
    float* dst = g_w2 + ((ic * 40 + oc) * 5 + ky) * 8;
    #pragma unroll
    for (int kx = 0; kx < 8; kx++) dst[kx] = (kx < 5) ? src[kx] : 0.f;
}

// ---------------- K1: conv1 (1->20, 5x5) + relu + maxpool2 ----------------
__global__ __launch_bounds__(256) void k_conv1(const float* __restrict__ x,
                                               const float* __restrict__ w,
                                               const float* __restrict__ bias) {
    __shared__ float img[784];
    __shared__ float ws[500];
    __shared__ float bs[20];
    int b = blockIdx.x, tid = threadIdx.x;
    const float* xb = x + b * 784;
    for (int i = tid; i < 784; i += 256) img[i] = xb[i];
    for (int i = tid; i < 500; i += 256) ws[i] = w[i];
    if (tid < 20) bs[tid] = bias[tid];
    __syncthreads();
    if (tid >= 240) return;
    int oc = tid / 12, py = tid % 12;
    float acc[2][24];
    float bv = bs[oc];
    #pragma unroll
    for (int cy = 0; cy < 2; cy++)
        #pragma unroll
        for (int ox = 0; ox < 24; ox++) acc[cy][ox] = bv;
    #pragma unroll 1
    for (int ky = 0; ky < 5; ky++) {
        float wk[5];
        #pragma unroll
        for (int kx = 0; kx < 5; kx++) wk[kx] = ws[(oc * 5 + ky) * 5 + kx];
        #pragma unroll
        for (int cy = 0; cy < 2; cy++) {
            const float* r = img + (2 * py + cy + ky) * 28;
            float rr[28];
            #pragma unroll
            for (int i = 0; i < 28; i++) rr[i] = r[i];
            #pragma unroll
            for (int kx = 0; kx < 5; kx++)
                #pragma unroll
                for (int ox = 0; ox < 24; ox++)
                    acc[cy][ox] += rr[ox + kx] * wk[kx];
        }
    }
    float* out = g_h1 + (b * 20 + oc) * 144 + py * 12;
    #pragma unroll
    for (int px = 0; px < 12; px++) {
        float v = fmaxf(fmaxf(acc[0][2 * px], acc[0][2 * px + 1]),
                        fmaxf(acc[1][2 * px], acc[1][2 * px + 1]));
        out[px] = fmaxf(v, 0.f);
    }
}

// ---------------- K2a: conv2 partial (10 ic per block half), pre-pool output -------
// grid (512 img, 2 ichalf), 160 threads = 40 oc x 4 py
__global__ __launch_bounds__(160) void k_conv2a() {
    __shared__ float in2[1440];    // 10 ic x 144
    __shared__ float ws[1600];     // one ic: 40 oc x 5 ky x 8
    int img = blockIdx.x, ih = blockIdx.y, tid = threadIdx.x;
    const float4* src4 = (const float4*)(g_h1 + img * 2880 + ih * 1440);
    float4* in24 = (float4*)in2;
    for (int t = tid; t < 360; t += 160) in24[t] = src4[t];

    int oc = tid / 4, py = tid % 4;
    float acc[2][8];
    #pragma unroll
    for (int cy = 0; cy < 2; cy++)
        #pragma unroll
        for (int ox = 0; ox < 8; ox++) acc[cy][ox] = 0.f;

    #pragma unroll 1
    for (int ic0 = 0; ic0 < 10; ic0++) {
        __syncthreads();
        const float4* wsrc = (const float4*)(g_w2 + (ih * 10 + ic0) * 1600);
        float4* ws4 = (float4*)ws;
        for (int t = tid; t < 400; t += 160) ws4[t] = wsrc[t];
        __syncthreads();
        #pragma unroll 1
        for (int ky = 0; ky < 5; ky++) {
            const float* wr = ws + (oc * 5 + ky) * 8;
            float wk[5];
            #pragma unroll
            for (int kx = 0; kx < 5; kx++) wk[kx] = wr[kx];
            #pragma unroll
            for (int cy = 0; cy < 2; cy++) {
                const float* r = in2 + ic0 * 144 + (2 * py + cy + ky) * 12;
                float rr[12];
                #pragma unroll
                for (int i = 0; i < 12; i++) rr[i] = r[i];
                #pragma unroll
                for (int kx = 0; kx < 5; kx++)
                    #pragma unroll
                    for (int ox = 0; ox < 8; ox++)
                        acc[cy][ox] += rr[ox + kx] * wk[kx];
            }
        }
    }
    float* out = g_p2 + ((ih * B + img) * 40 + oc) * 64;
    #pragma unroll
    for (int cy = 0; cy < 2; cy++)
        #pragma unroll
        for (int ox = 0; ox < 8; ox++)
            out[(2 * py + cy) * 8 + ox] = acc[cy][ox];
}

// ---------------- K2b: combine halves + bias + relu + maxpool2 ----------------
// grid 512, 640 threads = 40 oc x 16 pooled positions
__global__ __launch_bounds__(640) void k_conv2b(const float* __restrict__ bias) {
    int img = blockIdx.x, tid = threadIdx.x;
    int oc = tid / 16, p = tid % 16;
    int py = p / 4, px = p % 4;
    const float* p0 = g_p2 + ((0 * B + img) * 40 + oc) * 64;
    const float* p1 = g_p2 + ((1 * B + img) * 40 + oc) * 64;
    float bv = bias[oc];
    float v = -1e30f;
    #pragma unroll
    for (int cy = 0; cy < 2; cy++)
        #pragma unroll
        for (int cx = 0; cx < 2; cx++) {
            int idx = (2 * py + cy) * 8 + 2 * px + cx;
            v = fmaxf(v, p0[idx] + p1[idx] + bv);
        }
    g_feats[img * 640 + oc * 16 + py * 4 + px] = fmaxf(v, 0.f);
}

// ---------------- K3: M = feats @ T^T  [512,640]x[1024,640]^T -> [512,1024] -------
#define BM 64
#define BN 64
#define BKK 32
__global__ __launch_bounds__(256) void k_gemm(const float* __restrict__ Tm) {
    __shared__ float As[BKK][BM];
    __shared__ float Bs[BKK][BN];
    int bn = blockIdx.x, bm = blockIdx.y;
    int tid = threadIdx.x;
    int tx = tid % 16, ty = tid / 16;
    float acc[4][4] = {};
    const float* A = g_feats + (bm * BM) * FEAT;
    const float* Bmat = Tm + (bn * BN) * FEAT;
    for (int k0 = 0; k0 < FEAT; k0 += BKK) {
        #pragma unroll
        for (int i = 0; i < 2; i++) {
            int t = tid + i * 256;
            int m = t / 8, kq = t % 8;
            float4 v = *(const float4*)(A + m * FEAT + k0 + kq * 4);
            As[kq * 4 + 0][m] = v.x; As[kq * 4 + 1][m] = v.y;
            As[kq * 4 + 2][m] = v.z; As[kq * 4 + 3][m] = v.w;
            float4 u = *(const float4*)(Bmat + m * FEAT + k0 + kq * 4);
            Bs[kq * 4 + 0][m] = u.x; Bs[kq * 4 + 1][m] = u.y;
            Bs[kq * 4 + 2][m] = u.z; Bs[kq * 4 + 3][m] = u.w;
        }
        __syncthreads();
        #pragma unroll
        for (int kk = 0; kk < BKK; kk++) {
            float a[4], bb[4];
            #pragma unroll
            for (int i = 0; i < 4; i++) a[i] = As[kk][ty * 4 + i];
            #pragma unroll
            for (int j = 0; j < 4; j++) bb[j] = Bs[kk][tx * 4 + j];
            #pragma unroll
            for (int i = 0; i < 4; i++)
                #pragma unroll
                for (int j = 0; j < 4; j++) acc[i][j] += a[i] * bb[j];
        }
        __syncthreads();
    }
    #pragma unroll
    for (int i = 0; i < 4; i++)
        #pragma unroll
        for (int j = 0; j < 4; j++)
            g_M[(bm * BM + ty * 4 + i) * 1024 + bn * BN + tx * 4 + j] = acc[i][j];
}

// ---------------- K4: minibatch discrimination closeness (j-split partials) -------
// grid (64 bcol, 4 jchunk, 4 itile), 128 threads; smem = 128 j rows x 16 = 8KB
__global__ __launch_bounds__(128) void k_mbd() {
    __shared__ float s[128 * 16];
    int bcol = blockIdx.x, jc = blockIdx.y, it = blockIdx.z;
    int tid = threadIdx.x;
    int jbase = jc * 128;
    const float4* Ms = (const float4*)g_M;
    float4* s4 = (float4*)s;
    for (int t = tid; t < 128 * 4; t += 128) {
        int j = t >> 2, q = t & 3;
        s4[t] = Ms[((jbase + j) * 1024 + bcol * 16) / 4 + q];
    }
    int i = it * 128 + tid;
    float m[16];
    {
        const float4* mi = (const float4*)(g_M + i * 1024 + bcol * 16);
        #pragma unroll
        for (int q = 0; q < 4; q++) {
            float4 v = mi[q];
            m[q * 4 + 0] = v.x; m[q * 4 + 1] = v.y;
            m[q * 4 + 2] = v.z; m[q * 4 + 3] = v.w;
        }
    }
    __syncthreads();
    float acc = 0.f;
    #pragma unroll 4
    for (int j = 0; j < 128; j++) {
        float d = 0.f;
        const float* sj = s + j * 16;
        #pragma unroll
        for (int c = 0; c < 16; c++) d += fabsf(m[c] - sj[c]);
        acc += __expf(-d);
    }
    g_closep[(jc * B + i) * 64 + bcol] = acc;
}

// ---------------- K5: concat (sum closeness partials) + fc1 + relu + fc2 + sigmoid -
// grid 128 blocks x 4 batch rows, 256 threads
__global__ __launch_bounds__(256) void k_fc(const float* __restrict__ w1,
                                            const float* __restrict__ b1,
                                            const float* __restrict__ w2,
                                            const float* __restrict__ b2,
                                            float* __restrict__ out) {
    __shared__ float sin_[4][704];
    __shared__ float h[4][100];
    int row0 = blockIdx.x * 4;
    int tid = threadIdx.x;
    for (int t = tid; t < 4 * 704; t += 256) {
        int r = t / 704, c = t % 704;
        if (c < 640) {
            sin_[r][c] = g_feats[(row0 + r) * 640 + c];
        } else {
            int bcol = c - 640, i = row0 + r;
            float v = 0.f;
            #pragma unroll
            for (int jc = 0; jc < 4; jc++) v += g_closep[(jc * B + i) * 64 + bcol];
            sin_[r][c] = v;
        }
    }
    __syncthreads();
    for (int o = tid; o < 400; o += 256) {
        int r = o / 100, c = o % 100;
        const float4* wrow = (const float4*)(w1 + c * 704);
        const float4* xin = (const float4*)(&sin_[r][0]);
        float acc = 0.f;
        #pragma unroll 4
        for (int k = 0; k < 176; k++) {
            float4 wv = wrow[k], xv = xin[k];
            acc += wv.x * xv.x + wv.y * xv.y + wv.z * xv.z + wv.w * xv.w;
        }
        h[r][c] = fmaxf(acc + b1[c], 0.f);
    }
    __syncthreads();
    int w = tid / 32, lane = tid % 32;
    if (w < 4) {
        float a = 0.f;
        for (int c = lane; c < 100; c += 32) a += h[w][c] * w2[c];
        #pragma unroll
        for (int off = 16; off; off >>= 1) a += __shfl_down_sync(0xffffffffu, a, off);
        if (lane == 0) {
            float z = a + b2[0];
            out[row0 + w] = 1.f / (1.f + __expf(-z));
        }
    }
}

// ---------------- launch ----------------
extern "C" void kernel_launch(void* const* d_in, const int* in_sizes, int n_in,
                              void* d_out, int out_size) {
    const float* x       = (const float*)d_in[0];
    const float* conv1_w = (const float*)d_in[1];
    const float* conv1_b = (const float*)d_in[2];
    const float* conv2_w = (const float*)d_in[3];
    const float* conv2_b = (const float*)d_in[4];
    const float* Tm      = (const float*)d_in[5];
    const float* fc1_w   = (const float*)d_in[6];
    const float* fc1_b   = (const float*)d_in[7];
    const float* fc2_w   = (const float*)d_in[8];
    const float* fc2_b   = (const float*)d_in[9];
    float* out = (float*)d_out;

    k_repack<<<16, 256>>>(conv2_w);
    k_conv1<<<B, 256>>>(x, conv1_w, conv1_b);
    dim3 g2(B, 2);
    k_conv2a<<<g2, 160>>>();
    k_conv2b<<<B, 640>>>(conv2_b);
    dim3 g3(1024 / BN, B / BM);
    k_gemm<<<g3, 256>>>(Tm);
    dim3 g4(64, 4, 4);
    k_mbd<<<g4, 128>>>();
    k_fc<<<128, 256>>>(fc1_w, fc1_b, fc2_w, fc2_b, out);
}